// round 7
// baseline (speedup 1.0000x reference)
#include <cuda_runtime.h>

#define W 224
#define H 224
#define BC 192
#define STEPS 32
#define BANDS 5
#define RPB 45              // bands 0-3: 45 full rows; band 4: 43 full + bottom
#define TPB 256
#define NW 8
#define GRID (BC * BANDS)   // 960 blocks ~ one wave @ 6 blocks/SM

// g_hist[bc][j] accumulates the cumulative Euler characteristic at t_j.
__device__ int g_hist[BC * STEPS];
__device__ unsigned int g_count;

// Alive mask: bit j set iff t_j >= f, t_j = fl(j * fl(1/31)) (j<31), t_31 = 1.
// ceil anchor + two exact-grid fixups; bit-exact (rel_err==0, 4x validated).
__device__ __forceinline__ unsigned maskof(float f) {
    const float step = 1.0f / 31.0f;
    float fr = ceilf(f * 31.0f);                 // integral, in [0, 31]
    int g = (int)fr;
    if (__fmaf_rn(fr, step, -step) >= f) g--;    // t_{fr-1} >= f
    if (fr < 31.0f && fr * step < f)     g++;    // t_fr < f (t_31=1.0 covers rest)
    return 0xFFFFFFFFu << g;
}

__device__ __forceinline__ void csa5(unsigned c[5], unsigned x) {
    unsigned t;
    t = c[0] & x; c[0] ^= x; x = t;
    t = c[1] & x; c[1] ^= x; x = t;
    t = c[2] & x; c[2] ^= x; x = t;
    t = c[3] & x; c[3] ^= x; x = t;
    c[4] ^= x;
}
// 3:2 full-adder into weight-1 / weight-2 plane sets.
__device__ __forceinline__ void add3(unsigned A1[5], unsigned A2[5],
                                     unsigned x, unsigned y, unsigned z) {
    unsigned s = x ^ y ^ z;
    unsigned c = (x & y) | (x & z) | (y & z);
    csa5(A1, s);
    csa5(A2, c);
}
__device__ __forceinline__ void add2(unsigned A1[5], unsigned A2[5],
                                     unsigned x, unsigned y) {
    csa5(A1, x ^ y);
    csa5(A2, x & y);
}

// Warp 32x32 bit transpose: out lane j bit k = in lane k bit j.
__device__ __forceinline__ unsigned tr32(unsigned v, int lane) {
    unsigned w;
    w = __shfl_xor_sync(0xffffffffu, v, 16);
    v = (lane & 16) ? ((v & 0xFFFF0000u) | ((w >> 16) & 0x0000FFFFu))
                    : ((v & 0x0000FFFFu) | ((w << 16) & 0xFFFF0000u));
    w = __shfl_xor_sync(0xffffffffu, v, 8);
    v = (lane & 8)  ? ((v & 0xFF00FF00u) | ((w >> 8)  & 0x00FF00FFu))
                    : ((v & 0x00FF00FFu) | ((w << 8)  & 0xFF00FF00u));
    w = __shfl_xor_sync(0xffffffffu, v, 4);
    v = (lane & 4)  ? ((v & 0xF0F0F0F0u) | ((w >> 4)  & 0x0F0F0F0Fu))
                    : ((v & 0x0F0F0F0Fu) | ((w << 4)  & 0xF0F0F0F0u));
    w = __shfl_xor_sync(0xffffffffu, v, 2);
    v = (lane & 2)  ? ((v & 0xCCCCCCCCu) | ((w >> 2)  & 0x33333333u))
                    : ((v & 0x33333333u) | ((w << 2)  & 0xCCCCCCCCu));
    w = __shfl_xor_sync(0xffffffffu, v, 1);
    v = (lane & 1)  ? ((v & 0xAAAAAAAAu) | ((w >> 1)  & 0x55555555u))
                    : ((v & 0x55555555u) | ((w << 1)  & 0xAAAAAAAAu));
    return v;
}

struct St { const float* p; unsigned m, mr; };

// One pixel row: P (net +1 cells: vertex/h-edge) and N (net -1: v-edge/square).
//   interior: P = m & ~mr          N = (m & mn) & ~(mr & mnr)
//   edge col: P = m & ~mn          N = 0
__device__ __forceinline__ void rowPN(St& s, unsigned aM, unsigned hasRM,
                                      unsigned& P, unsigned& N, int ofs) {
    const unsigned mn  = maskof(__ldg(s.p + ofs));
    const unsigned mnr = __shfl_down_sync(0xffffffffu, mn, 1);
    const unsigned mrEff = (s.mr & hasRM) | (mn & ~hasRM);   // LOP3
    P = (s.m & ~mrEff) & aM;                                  // LOP3
    const unsigned t2 = (s.mr & mnr) | ~hasRM;                // LOP3
    N = (s.m & mn) & ~t2;                                     // LOP3
    s.m = mn; s.mr = mnr;
}

__global__ __launch_bounds__(TPB, 6) void ecc_kernel(const float* __restrict__ x,
                                                     float* __restrict__ out) {
    __shared__ int s_cnt[NW][STEPS];
    __shared__ bool s_last;

    const int tid  = threadIdx.x;
    const int wid  = tid >> 5;
    const int lane = tid & 31;
    const int col  = wid * 31 + lane;
    const int bc   = blockIdx.x / BANDS;
    const int band = blockIdx.x % BANDS;
    const int r0   = band * RPB;

    const bool act       = (lane < 31) && (col <= 223);
    const unsigned aM    = act ? 0xFFFFFFFFu : 0u;
    const unsigned hasRM = (act && col < 223) ? 0xFFFFFFFFu : 0u;
    const int colc = (col <= 223) ? col : 223;

    unsigned P1[5] = {0,0,0,0,0}, P2[5] = {0,0,0,0,0};
    unsigned N1[5] = {0,0,0,0,0}, N2[5] = {0,0,0,0,0};

    St s;
    s.p  = x + (size_t)bc * (H * W) + (size_t)r0 * W + colc;
    s.m  = maskof(__ldg(s.p));
    s.mr = __shfl_down_sync(0xffffffffu, s.m, 1);

    // bands 0-3: 45 rows = 15 triples; band 4: 42 rows here (14 triples).
    const int ntrip = (band == BANDS - 1) ? 14 : 15;
#pragma unroll 5
    for (int it = 0; it < ntrip; it++) {
        unsigned Pa, Na, Pb, Nb, Pc, Nc;
        rowPN(s, aM, hasRM, Pa, Na, W);
        rowPN(s, aM, hasRM, Pb, Nb, 2 * W);
        rowPN(s, aM, hasRM, Pc, Nc, 3 * W);
        s.p += 3 * W;
        add3(P1, P2, Pa, Pb, Pc);
        add3(N1, N2, Na, Nb, Nc);
    }

    if (band == BANDS - 1) {
        // row 222 (full) + row 223 (vertex + h-edge only).
        unsigned Pa, Na;
        rowPN(s, aM, hasRM, Pa, Na, W);
        const unsigned Pb = (s.m & ~(s.mr & hasRM)) & aM;   // bottom row
        add2(P1, P2, Pa, Pb);
        csa5(N1, Na);
    }

    // Epilogue: transpose planes, weighted popcounts -> chi @ bin `lane`.
    int cnt = 0;
#pragma unroll
    for (int i = 0; i < 5; i++) cnt += (int)__popc(tr32(P1[i], lane)) << i;
#pragma unroll
    for (int i = 0; i < 5; i++) cnt += (int)__popc(tr32(P2[i], lane)) << (i + 1);
#pragma unroll
    for (int i = 0; i < 5; i++) cnt -= (int)__popc(tr32(N1[i], lane)) << i;
#pragma unroll
    for (int i = 0; i < 5; i++) cnt -= (int)__popc(tr32(N2[i], lane)) << (i + 1);

    s_cnt[wid][lane] = cnt;
    __syncthreads();
    if (wid == 0) {
        int sum = 0;
#pragma unroll
        for (int w2 = 0; w2 < NW; w2++) sum += s_cnt[w2][lane];
        atomicAdd(&g_hist[bc * STEPS + lane], sum);
    }

    // Last-block-done: write out + reset scratch for next graph replay.
    __threadfence();
    __syncthreads();
    if (tid == 0)
        s_last = (atomicAdd(&g_count, 1u) == (unsigned)(GRID - 1));
    __syncthreads();

    if (s_last) {
        __threadfence();
        for (int g2 = wid; g2 < BC; g2 += NW) {
            const int vv = __ldcg(&g_hist[g2 * STEPS + lane]);
            out[g2 * STEPS + lane] = (float)vv;
            g_hist[g2 * STEPS + lane] = 0;
        }
        if (tid == 0) g_count = 0u;
    }
}

extern "C" void kernel_launch(void* const* d_in, const int* in_sizes, int n_in,
                              void* d_out, int out_size) {
    const float* x = (const float*)d_in[0];
    float* out = (float*)d_out;
    (void)in_sizes; (void)n_in; (void)out_size;
    ecc_kernel<<<GRID, TPB>>>(x, out);
}

// round 8
// speedup vs baseline: 1.2183x; 1.2183x over previous
#include <cuda_runtime.h>

#define W 224
#define H 224
#define BC 192
#define STEPS 32
#define BANDS 5
#define RPB 45               // bands 0-3: rows 45k..45k+44 ; band 4: 180..223
#define TPB 256
#define NW 8
#define GRID (BC * BANDS)    // 960 <= 148 SMs * 7 blocks = single wave

// g_hist[bc][j] = differential histogram; finalize does the 32-bin cumsum.
__device__ int g_hist[BC * STEPS];
__device__ unsigned int g_count;

// bin = searchsorted(linspace(0,1,32), f, 'left'), bit-exact (validated R6/R7):
// ceil anchor + two exact-grid fixups. Mostly fma-pipe ops (FMUL/FRND/FFMA/FSETP).
__device__ __forceinline__ int binof(float f) {
    const float step = 1.0f / 31.0f;
    float fr = ceilf(f * 31.0f);                 // integral, in [0, 31]
    int g = (int)fr;
    if (__fmaf_rn(fr, step, -step) >= f) g--;    // t_{fr-1} >= f
    if (fr < 31.0f && fr * step < f)     g++;    // t_fr < f  (t_31 = 1.0)
    return g;
}

__global__ __launch_bounds__(TPB) void ecc_kernel(const float* __restrict__ x,
                                                  float* __restrict__ out) {
    // Per-thread private histogram columns. 256 % 32 == 0 =>
    // bank(hist[j][t]) = t % 32 => conflict-free for any bin pattern.
    __shared__ int hist[STEPS][TPB];
    __shared__ bool s_last;

    const int tid  = threadIdx.x;
    const int wid  = tid >> 5;
    const int lane = tid & 31;
    const int col  = wid * 31 + lane;       // overlapped-warp column map
    const int bc   = blockIdx.x / BANDS;
    const int band = blockIdx.x % BANDS;
    const int r0   = band * RPB;

    const bool act  = (lane < 31) && (col <= 223);   // owns vertex `col`
    const bool hasR = act && (col < 223);            // h-edge / square exist
    const int  colc = (col <= 223) ? col : 223;

#pragma unroll
    for (int j = 0; j < STEPS; j++) hist[j][tid] = 0;
    __syncthreads();

    const float* p = x + (size_t)bc * (H * W) + (size_t)r0 * W + colc;

    int b  = binof(__ldg(p));
    int br = __shfl_down_sync(0xffffffffu, b, 1);    // valid for lanes 0..30

    const int nfull = (band == BANDS - 1) ? 43 : 45; // full rows (row below exists)
#pragma unroll 5
    for (int it = 0; it < nfull; it++) {
        p += W;
        const int nb  = binof(__ldg(p));
        const int nbr = __shfl_down_sync(0xffffffffu, nb, 1);

        // Cells at pixel (h, col): +v(b)  -he(e1)  -ve(e2)  +sq(q)
        const int e1 = max(b, br);
        const int e2 = max(b, nb);
        const int q  = max(e1, max(nb, nbr));
        if (act) {
            hist[b][tid]  += 1;
            hist[e2][tid] -= 1;
            if (hasR) {
                hist[e1][tid] -= 1;
                hist[q][tid]  += 1;
            }
        }
        b = nb; br = nbr;
    }

    if (band == BANDS - 1 && act) {                  // row 223: +v, -he only
        hist[b][tid] += 1;
        if (hasR) hist[max(b, br)][tid] -= 1;
    }
    __syncthreads();

    // Block reduction: warp w owns bins {w, w+8, w+16, w+24}.
    for (int j = wid; j < STEPS; j += NW) {
        int sum = 0;
#pragma unroll
        for (int t = lane; t < TPB; t += 32) sum += hist[j][t];
#pragma unroll
        for (int o = 16; o; o >>= 1) sum += __shfl_down_sync(0xffffffffu, sum, o);
        if (lane == 0) atomicAdd(&g_hist[bc * STEPS + j], sum);
    }

    // Last-block-done: cumsum -> out, reset scratch for next graph replay.
    __threadfence();
    __syncthreads();
    if (tid == 0)
        s_last = (atomicAdd(&g_count, 1u) == (unsigned)(GRID - 1));
    __syncthreads();

    if (s_last) {
        __threadfence();
        for (int g2 = wid; g2 < BC; g2 += NW) {
            int v = __ldcg(&g_hist[g2 * STEPS + lane]);
#pragma unroll
            for (int o = 1; o < 32; o <<= 1) {
                int t = __shfl_up_sync(0xffffffffu, v, o);
                if (lane >= o) v += t;
            }
            out[g2 * STEPS + lane] = (float)v;
            g_hist[g2 * STEPS + lane] = 0;
        }
        if (tid == 0) g_count = 0u;
    }
}

extern "C" void kernel_launch(void* const* d_in, const int* in_sizes, int n_in,
                              void* d_out, int out_size) {
    const float* x = (const float*)d_in[0];
    float* out = (float*)d_out;
    (void)in_sizes; (void)n_in; (void)out_size;
    ecc_kernel<<<GRID, TPB>>>(x, out);
}